// round 2
// baseline (speedup 1.0000x reference)
#include <cuda_runtime.h>
#include <cuda_bf16.h>
#include <cstdint>

// QuantizedLinear: y[b,o] = scale[o] * sum_i x[b,i] * (q[o,i] - 8)
// x: [512, 8192] f32 ; packed_weight: [8192, 4096] int32 (low byte = 2 nibbles,
// hi nibble = even in-feature, lo nibble = odd) ; scale: [8192] f32
// out: [512, 8192] f32 row-major.
//
// Round 1 baseline: smem-tiled fp32 SIMT GEMM, 128x128x16 tiles, 8x8 per thread.

#define BM 128
#define BN 128
#define BK 16
#define TM 8
#define TN 8
#define NTHREADS 256

static constexpr int M_DIM = 512;
static constexpr int N_DIM = 8192;
static constexpr int K_DIM = 8192;
static constexpr int KP    = K_DIM / 2;   // packed words per output row (4096)

__global__ __launch_bounds__(NTHREADS, 2)
void qlin_simt_kernel(const float* __restrict__ x,
                      const int*   __restrict__ packed,
                      const float* __restrict__ scale,
                      float*       __restrict__ y)
{
    __shared__ float Xs[BK][BM];      // [k][m]
    __shared__ float Ws[BK][BN];      // [k][n]  (dequantized q-8)

    const int tid = threadIdx.x;
    const int blockN = blockIdx.x * BN;
    const int blockM = blockIdx.y * BM;

    // thread tile coords: 16x16 thread grid, each does 8x8
    const int tx = tid & 15;          // n direction
    const int ty = tid >> 4;          // m direction

    float acc[TM][TN];
    #pragma unroll
    for (int i = 0; i < TM; i++)
        #pragma unroll
        for (int j = 0; j < TN; j++)
            acc[i][j] = 0.0f;

    // X tile load mapping: 128 rows x 16 cols = 512 float4; 2 per thread
    // idx = tid + r*256 -> m = idx/4, kq = idx%4
    // W tile load mapping: 128 rows x 8 packed words = 1024 words; 4 per thread (int4)
    // n = tid/2, jq = tid%2 -> words [jq*4 .. jq*4+3] of this k-block
    const int wn  = tid >> 1;
    const int wjq = tid & 1;
    const int* wrow = packed + (size_t)(blockN + wn) * KP;

    for (int k0 = 0; k0 < K_DIM; k0 += BK) {
        // ---- load X tile ----
        #pragma unroll
        for (int r = 0; r < 2; r++) {
            int idx = tid + r * NTHREADS;
            int m   = idx >> 2;
            int kq  = idx & 3;
            float4 v = *reinterpret_cast<const float4*>(
                x + (size_t)(blockM + m) * K_DIM + k0 + kq * 4);
            Xs[kq * 4 + 0][m] = v.x;
            Xs[kq * 4 + 1][m] = v.y;
            Xs[kq * 4 + 2][m] = v.z;
            Xs[kq * 4 + 3][m] = v.w;
        }

        // ---- load + dequant W tile (8 weights per thread-quarter, 2 int4 halves) ----
        {
            int4 p = *reinterpret_cast<const int4*>(wrow + (k0 >> 1) + wjq * 4);
            int kl = wjq * 8;
            int w;
            w = p.x;
            Ws[kl + 0][wn] = (float)((w >> 4) & 15) - 8.0f;
            Ws[kl + 1][wn] = (float)(w & 15) - 8.0f;
            w = p.y;
            Ws[kl + 2][wn] = (float)((w >> 4) & 15) - 8.0f;
            Ws[kl + 3][wn] = (float)(w & 15) - 8.0f;
            w = p.z;
            Ws[kl + 4][wn] = (float)((w >> 4) & 15) - 8.0f;
            Ws[kl + 5][wn] = (float)(w & 15) - 8.0f;
            w = p.w;
            Ws[kl + 6][wn] = (float)((w >> 4) & 15) - 8.0f;
            Ws[kl + 7][wn] = (float)(w & 15) - 8.0f;
        }

        __syncthreads();

        // ---- compute ----
        #pragma unroll
        for (int k = 0; k < BK; k++) {
            float a[TM], b[TN];
            float4 a0 = *reinterpret_cast<const float4*>(&Xs[k][ty * TM]);
            float4 a1 = *reinterpret_cast<const float4*>(&Xs[k][ty * TM + 4]);
            a[0]=a0.x; a[1]=a0.y; a[2]=a0.z; a[3]=a0.w;
            a[4]=a1.x; a[5]=a1.y; a[6]=a1.z; a[7]=a1.w;
            float4 b0 = *reinterpret_cast<const float4*>(&Ws[k][tx * TN]);
            float4 b1 = *reinterpret_cast<const float4*>(&Ws[k][tx * TN + 4]);
            b[0]=b0.x; b[1]=b0.y; b[2]=b0.z; b[3]=b0.w;
            b[4]=b1.x; b[5]=b1.y; b[6]=b1.z; b[7]=b1.w;

            #pragma unroll
            for (int i = 0; i < TM; i++)
                #pragma unroll
                for (int j = 0; j < TN; j++)
                    acc[i][j] = fmaf(a[i], b[j], acc[i][j]);
        }

        __syncthreads();
    }

    // ---- epilogue: apply per-output-column scale, write f32 ----
    float s[TN];
    #pragma unroll
    for (int j = 0; j < TN; j++)
        s[j] = scale[blockN + tx * TN + j];

    #pragma unroll
    for (int i = 0; i < TM; i++) {
        int row = blockM + ty * TM + i;
        float* out = y + (size_t)row * N_DIM + blockN + tx * TN;
        float4 o0, o1;
        o0.x = acc[i][0] * s[0];
        o0.y = acc[i][1] * s[1];
        o0.z = acc[i][2] * s[2];
        o0.w = acc[i][3] * s[3];
        o1.x = acc[i][4] * s[4];
        o1.y = acc[i][5] * s[5];
        o1.z = acc[i][6] * s[6];
        o1.w = acc[i][7] * s[7];
        *reinterpret_cast<float4*>(out)     = o0;
        *reinterpret_cast<float4*>(out + 4) = o1;
    }
}

extern "C" void kernel_launch(void* const* d_in, const int* in_sizes, int n_in,
                              void* d_out, int out_size)
{
    const float* x      = (const float*)d_in[0];
    const int*   packed = (const int*)  d_in[1];
    const float* scale  = (const float*)d_in[2];
    float*       y      = (float*)d_out;

    dim3 grid(N_DIM / BN, M_DIM / BM);   // (64, 4)
    dim3 block(NTHREADS);
    qlin_simt_kernel<<<grid, block>>>(x, packed, scale, y);
}

// round 4
// speedup vs baseline: 6.4141x; 6.4141x over previous
#include <cuda_runtime.h>
#include <cuda_fp16.h>
#include <cstdint>

// QuantizedLinear on GB300 (sm_103a harness, compute_103 virtual arch):
//   y[b,o] = scale[o] * sum_k x[b,k] * (q[o,k] - 8)
// tcgen05 is unavailable (ptxas target sm_103 rejects 103a features), so this
// uses the legacy tensor-core path: mma.sync.m16n8k16 fp16->fp32.
// Stage 1: x f32 -> fp16 scratch (8 MB)
// Stage 2: repack weights to dense interleaved nibbles (33.5 MB):
//          word j: bits[4p:4p+4]=q_{8j+2p}, bits[16+4p:20+4p]=q_{8j+2p+1}
//          -> one SHR + one LOP3 + one sub.f16x2 per dequantized half2 (exact)
// Stage 3: 128x128x(KC=64) CTA-tiled HMMA GEMM, 3-stage cp.async pipeline,
//          8 warps (2x4) each computing 64x32, fp32 accum, fp32 scale epilogue.

static constexpr int M_DIM = 512;
static constexpr int N_DIM = 8192;
static constexpr int K_DIM = 8192;

static constexpr int BM = 128;
static constexpr int BN = 128;
static constexpr int KC = 64;                     // halves per chunk (128 B rows)
static constexpr int STAGES = 3;
static constexpr int NCHUNK = K_DIM / KC;         // 128

static constexpr int A_BYTES = BM * 128;          // 16 KB
static constexpr int B_BYTES = BN * 128;          // 16 KB
static constexpr int STAGE_BYTES = A_BYTES + B_BYTES;       // 32 KB
static constexpr int SMEM_BYTES = STAGES * STAGE_BYTES;     // 96 KB

// -------- scratch (device globals; no runtime allocation) --------
__device__ __align__(16) __half    g_xh [(size_t)M_DIM * K_DIM];          // 8 MB
__device__ __align__(16) unsigned  g_wpk[(size_t)N_DIM * (K_DIM / 8)];    // 33.5 MB

// ---------------- helpers ----------------
__device__ __forceinline__ uint32_t smem_u32(const void* p) {
    uint32_t a;
    asm("{ .reg .u64 t; cvta.to.shared.u64 t, %1; cvt.u32.u64 %0, t; }"
        : "=r"(a) : "l"(p));
    return a;
}

__device__ __forceinline__ uint32_t sw128(uint32_t off) {
    return off ^ ((off >> 3) & 0x70u);
}

// (1024+q) - 1032 = q - 8, exact in fp16, both lanes
__device__ __forceinline__ uint32_t dq_sub(uint32_t v) {
    uint32_t r;
    asm("sub.rn.f16x2 %0, %1, %2;" : "=r"(r) : "r"(v), "r"(0x64086408u));
    return r;
}

__device__ __forceinline__ void cp_async16(uint32_t dst, const void* src) {
    asm volatile("cp.async.cg.shared.global [%0], [%1], 16;"
                 :: "r"(dst), "l"(src) : "memory");
}
__device__ __forceinline__ void cp_commit() {
    asm volatile("cp.async.commit_group;" ::: "memory");
}
template <int N>
__device__ __forceinline__ void cp_wait() {
    asm volatile("cp.async.wait_group %0;" :: "n"(N) : "memory");
}

__device__ __forceinline__ void ldmatrix4(uint32_t& r0, uint32_t& r1,
                                          uint32_t& r2, uint32_t& r3,
                                          uint32_t addr) {
    asm volatile("ldmatrix.sync.aligned.m8n8.x4.shared.b16 {%0,%1,%2,%3}, [%4];"
                 : "=r"(r0), "=r"(r1), "=r"(r2), "=r"(r3) : "r"(addr));
}

__device__ __forceinline__ void hmma(float& d0, float& d1, float& d2, float& d3,
                                     uint32_t a0, uint32_t a1, uint32_t a2, uint32_t a3,
                                     uint32_t b0, uint32_t b1) {
    asm volatile(
        "mma.sync.aligned.m16n8k16.row.col.f32.f16.f16.f32 "
        "{%0,%1,%2,%3}, {%4,%5,%6,%7}, {%8,%9}, {%0,%1,%2,%3};"
        : "+f"(d0), "+f"(d1), "+f"(d2), "+f"(d3)
        : "r"(a0), "r"(a1), "r"(a2), "r"(a3), "r"(b0), "r"(b1));
}

// ---------------- Stage 1: x f32 -> fp16 ----------------
__global__ void convert_x_kernel(const float* __restrict__ x) {
    int i = blockIdx.x * blockDim.x + threadIdx.x;      // float4 index
    float4 v = reinterpret_cast<const float4*>(x)[i];
    reinterpret_cast<__half2*>(g_xh)[2 * i + 0] = __floats2half2_rn(v.x, v.y);
    reinterpret_cast<__half2*>(g_xh)[2 * i + 1] = __floats2half2_rn(v.z, v.w);
}

// ---------------- Stage 2: repack to dense interleaved nibbles ----------------
__global__ void repack_w_kernel(const int* __restrict__ packed) {
    int j = blockIdx.x * blockDim.x + threadIdx.x;
    uint4 p = reinterpret_cast<const uint4*>(packed)[j];   // input words 4j..4j+3
    unsigned out = 0;
    out |= ((p.x >> 4) & 15u)         | ((p.x & 15u) << 16);
    out |= (((p.y >> 4) & 15u) << 4)  | ((p.y & 15u) << 20);
    out |= (((p.z >> 4) & 15u) << 8)  | ((p.z & 15u) << 24);
    out |= (((p.w >> 4) & 15u) << 12) | ((p.w & 15u) << 28);
    g_wpk[j] = out;
}

// ---------------- Stage 3: HMMA GEMM ----------------
__global__ __launch_bounds__(256, 2)
void qgemm_kernel(const float* __restrict__ scale, float* __restrict__ y) {
    extern __shared__ __align__(1024) char sb[];
    const uint32_t sb32 = smem_u32(sb);

    const int tid = threadIdx.x;
    const int wid = tid >> 5;
    const int lid = tid & 31;
    const int N0 = blockIdx.x * BN;
    const int M0 = blockIdx.y * BM;

    const int wm = wid >> 2;           // 0..1 -> m offset wm*64
    const int wn = wid & 3;            // 0..3 -> n offset wn*32

    // producer mappings
    const int a_m = tid >> 3;          // unused directly; per-seg below
    (void)a_m;
    const __half* xb = g_xh + (size_t)M0 * K_DIM;
    const int bn_row = tid >> 1;                       // 0..127
    const int bq     = tid & 1;                        // word quarter (0..1)
    const unsigned* wrow = g_wpk + (size_t)(N0 + bn_row) * (K_DIM / 8) + bq * 4;

    float acc[4][4][4];
    #pragma unroll
    for (int i = 0; i < 4; i++)
        #pragma unroll
        for (int j = 0; j < 4; j++)
            #pragma unroll
            for (int v = 0; v < 4; v++)
                acc[i][j][v] = 0.0f;

    // ---- producer lambdas (manually inlined) ----
    // A: 1024 16B segs / stage; 4 per thread
    // B: row bn_row, words [bq*4 .. bq*4+3] of the chunk

    // prologue: fill stages 0..STAGES-2
    #pragma unroll
    for (int s = 0; s < STAGES - 1; s++) {
        const int k0 = s * KC;
        uint32_t As = sb32 + s * STAGE_BYTES;
        uint32_t Bs = As + A_BYTES;
        #pragma unroll
        for (int i = 0; i < 4; i++) {
            int seg = tid + i * 256;
            int m = seg >> 3, j = seg & 7;
            cp_async16(As + sw128((uint32_t)(m * 128 + j * 16)),
                       xb + (size_t)m * K_DIM + k0 + j * 8);
        }
        cp_commit();
        uint4 p = *reinterpret_cast<const uint4*>(wrow + (k0 >> 3));
        unsigned wbuf[4] = {p.x, p.y, p.z, p.w};
        #pragma unroll
        for (int w = 0; w < 4; w++) {
            unsigned ww = wbuf[w];
            uint4 q;
            q.x = dq_sub(( ww        & 0x000F000Fu) | 0x64006400u);
            q.y = dq_sub(((ww >> 4)  & 0x000F000Fu) | 0x64006400u);
            q.z = dq_sub(((ww >> 8)  & 0x000F000Fu) | 0x64006400u);
            q.w = dq_sub(((ww >> 12) & 0x000F000Fu) | 0x64006400u);
            *reinterpret_cast<uint4*>(sb + (Bs - sb32) +
                sw128((uint32_t)(bn_row * 128 + (bq * 4 + w) * 16))) = q;
        }
    }

    const uint32_t a_warp_base = (uint32_t)(wm * 64 * 128);
    const uint32_t b_warp_base = (uint32_t)(wn * 32 * 128);

    for (int c = 0; c < NCHUNK; c++) {
        const int fc = c + STAGES - 1;
        const int fst = fc % STAGES;
        uint4 p;
        bool fetch = (fc < NCHUNK);
        if (fetch) {
            const int k0 = fc * KC;
            uint32_t As = sb32 + fst * STAGE_BYTES;
            #pragma unroll
            for (int i = 0; i < 4; i++) {
                int seg = tid + i * 256;
                int m = seg >> 3, j = seg & 7;
                cp_async16(As + sw128((uint32_t)(m * 128 + j * 16)),
                           xb + (size_t)m * K_DIM + k0 + j * 8);
            }
            p = *reinterpret_cast<const uint4*>(wrow + (k0 >> 3));
        }
        cp_commit();
        cp_wait<STAGES - 1>();
        __syncthreads();

        // ---- compute chunk c from stage c%STAGES ----
        {
            const int st = c % STAGES;
            const uint32_t As = sb32 + st * STAGE_BYTES + a_warp_base;
            const uint32_t Bs = sb32 + st * STAGE_BYTES + A_BYTES + b_warp_base;

            #pragma unroll
            for (int kk = 0; kk < 4; kk++) {
                uint32_t a[4][4];
                #pragma unroll
                for (int i = 0; i < 4; i++) {
                    uint32_t addr = As + sw128((uint32_t)(
                        (i * 16 + (lid & 15)) * 128 + kk * 32 + (lid >> 4) * 16));
                    ldmatrix4(a[i][0], a[i][1], a[i][2], a[i][3], addr);
                }
                uint32_t b[4][2];
                #pragma unroll
                for (int g = 0; g < 2; g++) {
                    int ql = lid >> 3;            // 0..3
                    int row = g * 16 + (ql >> 1) * 8 + (lid & 7);
                    int kh  = ql & 1;
                    uint32_t addr = Bs + sw128((uint32_t)(
                        row * 128 + kk * 32 + kh * 16));
                    ldmatrix4(b[2*g][0], b[2*g][1], b[2*g+1][0], b[2*g+1][1], addr);
                }
                #pragma unroll
                for (int i = 0; i < 4; i++)
                    #pragma unroll
                    for (int j = 0; j < 4; j++)
                        hmma(acc[i][j][0], acc[i][j][1], acc[i][j][2], acc[i][j][3],
                             a[i][0], a[i][1], a[i][2], a[i][3],
                             b[j][0], b[j][1]);
            }
        }

        // ---- deferred B dequant + STS for stage fst (hides under HMMA drain) ----
        if (fetch) {
            uint32_t Bs_off = fst * STAGE_BYTES + A_BYTES;
            unsigned wbuf[4] = {p.x, p.y, p.z, p.w};
            #pragma unroll
            for (int w = 0; w < 4; w++) {
                unsigned ww = wbuf[w];
                uint4 q;
                q.x = dq_sub(( ww        & 0x000F000Fu) | 0x64006400u);
                q.y = dq_sub(((ww >> 4)  & 0x000F000Fu) | 0x64006400u);
                q.z = dq_sub(((ww >> 8)  & 0x000F000Fu) | 0x64006400u);
                q.w = dq_sub(((ww >> 12) & 0x000F000Fu) | 0x64006400u);
                *reinterpret_cast<uint4*>(sb + Bs_off +
                    sw128((uint32_t)(bn_row * 128 + (bq * 4 + w) * 16))) = q;
            }
        }
        __syncthreads();
    }

    // ---- epilogue: scale + store fp32 ----
    #pragma unroll
    for (int i = 0; i < 4; i++) {
        int m0 = M0 + wm * 64 + i * 16 + (lid >> 2);
        #pragma unroll
        for (int j = 0; j < 4; j++) {
            int n = N0 + wn * 32 + j * 8 + 2 * (lid & 3);
            float2 s = *reinterpret_cast<const float2*>(scale + n);
            float2 o0, o1;
            o0.x = acc[i][j][0] * s.x;
            o0.y = acc[i][j][1] * s.y;
            o1.x = acc[i][j][2] * s.x;
            o1.y = acc[i][j][3] * s.y;
            *reinterpret_cast<float2*>(y + (size_t)m0 * N_DIM + n) = o0;
            *reinterpret_cast<float2*>(y + (size_t)(m0 + 8) * N_DIM + n) = o1;
        }
    }
}

// ---------------- launch ----------------
extern "C" void kernel_launch(void* const* d_in, const int* in_sizes, int n_in,
                              void* d_out, int out_size) {
    const float* x      = (const float*)d_in[0];
    const int*   packed = (const int*)  d_in[1];
    const float* scale  = (const float*)d_in[2];
    float*       y      = (float*)d_out;

    convert_x_kernel<<<(M_DIM * (K_DIM / 4)) / 256, 256>>>(x);
    repack_w_kernel<<<((size_t)N_DIM * (K_DIM / 8)) / 256, 256>>>(packed);

    static bool attr_set = false;
    if (!attr_set) {
        cudaFuncSetAttribute(qgemm_kernel,
                             cudaFuncAttributeMaxDynamicSharedMemorySize, SMEM_BYTES);
        attr_set = true;
    }
    dim3 grid(N_DIM / BN, M_DIM / BM);   // (64, 4) = 256 CTAs
    qgemm_kernel<<<grid, 256, SMEM_BYTES>>>(scale, y);
}

// round 5
// speedup vs baseline: 6.6642x; 1.0390x over previous
#include <cuda_runtime.h>
#include <cuda_fp16.h>
#include <cstdint>

// QuantizedLinear on GB300 (sm_103a harness, compute_103 virtual arch -> legacy
// mma.sync.m16n8k16 tensor path; tcgen05 PTX rejected by ptxas at this target).
//   y[b,o] = scale[o] * sum_k x[b,k] * (q[o,k] - 8)
//
// Stage 1: x f32 -> fp16 scratch (8 MB)
// Stage 2: repack weights to dense interleaved nibbles (33.5 MB):
//          word j of row n covers k=8j..8j+7: bits[4p:4p+4]=q_{8j+2p} (even k),
//          bits[16+4p:20+4p]=q_{8j+2p+1} (odd k). A single (w>>4p)&0x000F000F
//          | 0x64006400 then sub.f16x2(1032) yields the exact {even,odd} fp16
//          pair in mma-fragment register order.
// Stage 3: CTA 128x256, KC=64, 4-stage cp.async pipeline. A: fp16 SW128 smem +
//          ldmatrix. B: stays PACKED in smem (48B-padded rows, conflict-free);
//          consumer warps build B fragments via LDS.64 broadcast + 3-op dequant.
//          8 warps, 64x64 warp tile, fp32 accum, fp32 scale epilogue.

static constexpr int M_DIM = 512;
static constexpr int N_DIM = 8192;
static constexpr int K_DIM = 8192;

static constexpr int BM = 128;
static constexpr int BN = 256;
static constexpr int KC = 64;                      // k per chunk
static constexpr int STAGES = 4;
static constexpr int NCHUNK = K_DIM / KC;          // 128
static constexpr int KW = K_DIM / 8;               // packed words per row (1024)

static constexpr int A_BYTES  = BM * 128;          // 16384 (fp16 SW128)
static constexpr int BROW     = 48;                // padded row stride (8 words + pad)
static constexpr int BP_BYTES = BN * BROW;         // 12288
static constexpr int STAGE_BYTES = A_BYTES + BP_BYTES;       // 28672
static constexpr int SMEM_BYTES  = STAGES * STAGE_BYTES;     // 114688

// -------- scratch (device globals; no runtime allocation) --------
__device__ __align__(16) __half    g_xh [(size_t)M_DIM * K_DIM];   // 8 MB
__device__ __align__(16) unsigned  g_wpk[(size_t)N_DIM * KW];      // 33.5 MB

// ---------------- helpers ----------------
__device__ __forceinline__ uint32_t smem_u32(const void* p) {
    uint32_t a;
    asm("{ .reg .u64 t; cvta.to.shared.u64 t, %1; cvt.u32.u64 %0, t; }"
        : "=r"(a) : "l"(p));
    return a;
}

__device__ __forceinline__ uint32_t sw128(uint32_t off) {
    return off ^ ((off >> 3) & 0x70u);
}

// (1024+q) - 1032 = q - 8, exact in fp16, both lanes
__device__ __forceinline__ uint32_t dq_sub(uint32_t v) {
    uint32_t r;
    asm("sub.rn.f16x2 %0, %1, %2;" : "=r"(r) : "r"(v), "r"(0x64086408u));
    return r;
}

__device__ __forceinline__ void cp_async16(uint32_t dst, const void* src) {
    asm volatile("cp.async.cg.shared.global [%0], [%1], 16;"
                 :: "r"(dst), "l"(src) : "memory");
}
__device__ __forceinline__ void cp_commit() {
    asm volatile("cp.async.commit_group;" ::: "memory");
}
template <int N>
__device__ __forceinline__ void cp_wait() {
    asm volatile("cp.async.wait_group %0;" :: "n"(N) : "memory");
}

__device__ __forceinline__ void ldmatrix4(uint32_t& r0, uint32_t& r1,
                                          uint32_t& r2, uint32_t& r3,
                                          uint32_t addr) {
    asm volatile("ldmatrix.sync.aligned.m8n8.x4.shared.b16 {%0,%1,%2,%3}, [%4];"
                 : "=r"(r0), "=r"(r1), "=r"(r2), "=r"(r3) : "r"(addr));
}

__device__ __forceinline__ void hmma(float* d,
                                     uint32_t a0, uint32_t a1, uint32_t a2, uint32_t a3,
                                     uint32_t b0, uint32_t b1) {
    asm volatile(
        "mma.sync.aligned.m16n8k16.row.col.f32.f16.f16.f32 "
        "{%0,%1,%2,%3}, {%4,%5,%6,%7}, {%8,%9}, {%0,%1,%2,%3};"
        : "+f"(d[0]), "+f"(d[1]), "+f"(d[2]), "+f"(d[3])
        : "r"(a0), "r"(a1), "r"(a2), "r"(a3), "r"(b0), "r"(b1));
}

// ---------------- Stage 1: x f32 -> fp16 ----------------
__global__ void convert_x_kernel(const float* __restrict__ x) {
    int i = blockIdx.x * blockDim.x + threadIdx.x;      // float4 index
    float4 v = reinterpret_cast<const float4*>(x)[i];
    reinterpret_cast<__half2*>(g_xh)[2 * i + 0] = __floats2half2_rn(v.x, v.y);
    reinterpret_cast<__half2*>(g_xh)[2 * i + 1] = __floats2half2_rn(v.z, v.w);
}

// ---------------- Stage 2: repack to dense interleaved nibbles ----------------
__global__ void repack_w_kernel(const int* __restrict__ packed) {
    int j = blockIdx.x * blockDim.x + threadIdx.x;
    uint4 p = reinterpret_cast<const uint4*>(packed)[j];   // input words 4j..4j+3
    unsigned out = 0;
    out |= ((p.x >> 4) & 15u)         | ((p.x & 15u) << 16);
    out |= (((p.y >> 4) & 15u) << 4)  | ((p.y & 15u) << 20);
    out |= (((p.z >> 4) & 15u) << 8)  | ((p.z & 15u) << 24);
    out |= (((p.w >> 4) & 15u) << 12) | ((p.w & 15u) << 28);
    g_wpk[j] = out;
}

// ---------------- Stage 3: HMMA GEMM ----------------
__global__ __launch_bounds__(256, 1)
void qgemm_kernel(const float* __restrict__ scale, float* __restrict__ y) {
    extern __shared__ __align__(1024) char sb[];
    const uint32_t sb32 = smem_u32(sb);

    const int tid = threadIdx.x;
    const int wid = tid >> 5;
    const int lid = tid & 31;
    const int N0 = blockIdx.x * BN;
    const int M0 = blockIdx.y * BM;

    const int wm = wid >> 2;            // 0..1 : m offset wm*64
    const int wn = wid & 3;             // 0..3 : n offset wn*64

    const __half* xb = g_xh + (size_t)M0 * K_DIM;
    // B producer mapping: 512 16B segs/chunk; 2 per thread
    // idx = tid + i*256 -> n = idx>>1 (0..255), h = idx&1
    const unsigned* wbase = g_wpk + (size_t)N0 * KW;

    float acc[4][8][4];
    #pragma unroll
    for (int i = 0; i < 4; i++)
        #pragma unroll
        for (int j = 0; j < 8; j++)
            #pragma unroll
            for (int v = 0; v < 4; v++)
                acc[i][j][v] = 0.0f;

    // ---- prologue: fill STAGES-1 stages ----
    #pragma unroll
    for (int s = 0; s < STAGES - 1; s++) {
        const int k0 = s * KC;
        const uint32_t As = sb32 + s * STAGE_BYTES;
        const uint32_t Bs = As + A_BYTES;
        #pragma unroll
        for (int i = 0; i < 4; i++) {                   // A: 1024 segs
            int seg = tid + i * 256;
            int m = seg >> 3, j = seg & 7;
            cp_async16(As + sw128((uint32_t)(m * 128 + j * 16)),
                       xb + (size_t)m * K_DIM + k0 + j * 8);
        }
        #pragma unroll
        for (int i = 0; i < 2; i++) {                   // B packed: 512 segs
            int idx = tid + i * 256;
            int n = idx >> 1, h = idx & 1;
            cp_async16(Bs + (uint32_t)(n * BROW + h * 16),
                       wbase + (size_t)n * KW + (k0 >> 3) + h * 4);
        }
        cp_commit();
    }

    const uint32_t a_warp = (uint32_t)(wm * 64 * 128);
    const int b_shift = (lid & 3) * 4;
    const int b_nrow_base = wn * 64 + (lid >> 2);

    for (int c = 0; c < NCHUNK; c++) {
        // ---- fetch chunk c+STAGES-1 into stage (c+STAGES-1)%STAGES ----
        const int fc = c + STAGES - 1;
        if (fc < NCHUNK) {
            const int fst = fc % STAGES;
            const int k0 = fc * KC;
            const uint32_t As = sb32 + fst * STAGE_BYTES;
            const uint32_t Bs = As + A_BYTES;
            #pragma unroll
            for (int i = 0; i < 4; i++) {
                int seg = tid + i * 256;
                int m = seg >> 3, j = seg & 7;
                cp_async16(As + sw128((uint32_t)(m * 128 + j * 16)),
                           xb + (size_t)m * K_DIM + k0 + j * 8);
            }
            #pragma unroll
            for (int i = 0; i < 2; i++) {
                int idx = tid + i * 256;
                int n = idx >> 1, h = idx & 1;
                cp_async16(Bs + (uint32_t)(n * BROW + h * 16),
                           wbase + (size_t)n * KW + (k0 >> 3) + h * 4);
            }
        }
        cp_commit();
        cp_wait<STAGES - 1>();
        __syncthreads();

        // ---- compute chunk c from stage c%STAGES ----
        {
            const int st = c % STAGES;
            const uint32_t As = sb32 + st * STAGE_BYTES + a_warp;
            const char*    Bp = sb + st * STAGE_BYTES + A_BYTES;

            #pragma unroll
            for (int kk = 0; kk < 4; kk++) {
                uint32_t a[4][4];
                #pragma unroll
                for (int i = 0; i < 4; i++) {
                    uint32_t addr = As + sw128((uint32_t)(
                        (i * 16 + (lid & 15)) * 128 + kk * 32 + (lid >> 4) * 16));
                    ldmatrix4(a[i][0], a[i][1], a[i][2], a[i][3], addr);
                }
                #pragma unroll
                for (int jn = 0; jn < 8; jn++) {
                    int nrow = b_nrow_base + jn * 8;
                    uint2 w = *reinterpret_cast<const uint2*>(
                        Bp + nrow * BROW + kk * 8);
                    uint32_t b0 = dq_sub(((w.x >> b_shift) & 0x000F000Fu) | 0x64006400u);
                    uint32_t b1 = dq_sub(((w.y >> b_shift) & 0x000F000Fu) | 0x64006400u);
                    #pragma unroll
                    for (int i = 0; i < 4; i++)
                        hmma(acc[i][jn], a[i][0], a[i][1], a[i][2], a[i][3], b0, b1);
                }
            }
        }
        __syncthreads();
    }

    // ---- epilogue: scale + store fp32 ----
    #pragma unroll
    for (int i = 0; i < 4; i++) {
        int m0 = M0 + wm * 64 + i * 16 + (lid >> 2);
        #pragma unroll
        for (int j = 0; j < 8; j++) {
            int n = N0 + wn * 64 + j * 8 + 2 * (lid & 3);
            float2 s = *reinterpret_cast<const float2*>(scale + n);
            float2 o0, o1;
            o0.x = acc[i][j][0] * s.x;
            o0.y = acc[i][j][1] * s.y;
            o1.x = acc[i][j][2] * s.x;
            o1.y = acc[i][j][3] * s.y;
            *reinterpret_cast<float2*>(y + (size_t)m0 * N_DIM + n) = o0;
            *reinterpret_cast<float2*>(y + (size_t)(m0 + 8) * N_DIM + n) = o1;
        }
    }
}

// ---------------- launch ----------------
extern "C" void kernel_launch(void* const* d_in, const int* in_sizes, int n_in,
                              void* d_out, int out_size) {
    const float* x      = (const float*)d_in[0];
    const int*   packed = (const int*)  d_in[1];
    const float* scale  = (const float*)d_in[2];
    float*       y      = (float*)d_out;

    convert_x_kernel<<<(M_DIM * (K_DIM / 4)) / 256, 256>>>(x);
    repack_w_kernel<<<((size_t)N_DIM * (K_DIM / 8)) / 256, 256>>>(packed);

    static bool attr_set = false;
    if (!attr_set) {
        cudaFuncSetAttribute(qgemm_kernel,
                             cudaFuncAttributeMaxDynamicSharedMemorySize, SMEM_BYTES);
        attr_set = true;
    }
    dim3 grid(N_DIM / BN, M_DIM / BM);   // (32, 4) = 128 CTAs
    qgemm_kernel<<<grid, 256, SMEM_BYTES>>>(scale, y);
}

// round 6
// speedup vs baseline: 7.3562x; 1.1038x over previous
#include <cuda_runtime.h>
#include <cuda_fp16.h>
#include <cstdint>

// QuantizedLinear on GB300 (sm_103a harness, compute_103 virtual arch -> legacy
// mma.sync.m16n8k16 tensor path; tcgen05 PTX is rejected by ptxas here).
//   y[b,o] = scale[o] * sum_k x[b,k] * (q[o,k] - 8)
//
// Round 6: W fully dequantized to fp16 in the prepass (134 MB scratch) so the
// GEMM consumer does ldmatrix-only operand fetch (no per-fragment dequant ALU).
// Single fused prep kernel (x->fp16 + W->fp16), then 128x256 HMMA GEMM,
// KC=64, 4-stage cp.async pipeline, 8 warps @ 64x64, fp32 accum + scale.

static constexpr int M_DIM = 512;
static constexpr int N_DIM = 8192;
static constexpr int K_DIM = 8192;

static constexpr int BM = 128;
static constexpr int BN = 256;
static constexpr int KC = 64;
static constexpr int STAGES = 4;
static constexpr int NCHUNK = K_DIM / KC;          // 128

static constexpr int A_BYTES = BM * 128;           // 16 KB (fp16 SW128)
static constexpr int B_BYTES = BN * 128;           // 32 KB (fp16 SW128)
static constexpr int STAGE_BYTES = A_BYTES + B_BYTES;      // 48 KB
static constexpr int SMEM_BYTES  = STAGES * STAGE_BYTES;   // 192 KB

// prep kernel partition
static constexpr int XCONV_BLOCKS = (M_DIM * K_DIM / 4) / 256;            // 4096
static constexpr int WDEQ_BLOCKS  = (N_DIM * (K_DIM / 2) / 4) / 256;      // 16384... (threads handle 4 words = 8 values)
static constexpr int PREP_BLOCKS  = XCONV_BLOCKS + WDEQ_BLOCKS;

// -------- scratch (device globals; no runtime allocation) --------
__device__ __align__(16) __half g_xh[(size_t)M_DIM * K_DIM];    // 8 MB
__device__ __align__(16) __half g_wh[(size_t)N_DIM * K_DIM];    // 134 MB

// ---------------- helpers ----------------
__device__ __forceinline__ uint32_t smem_u32(const void* p) {
    uint32_t a;
    asm("{ .reg .u64 t; cvta.to.shared.u64 t, %1; cvt.u32.u64 %0, t; }"
        : "=r"(a) : "l"(p));
    return a;
}

__device__ __forceinline__ uint32_t sw128(uint32_t off) {
    return off ^ ((off >> 3) & 0x70u);
}

// (1024+q) - 1032 = q - 8, exact in fp16, both lanes
__device__ __forceinline__ uint32_t dq_sub(uint32_t v) {
    uint32_t r;
    asm("sub.rn.f16x2 %0, %1, %2;" : "=r"(r) : "r"(v), "r"(0x64086408u));
    return r;
}

__device__ __forceinline__ void cp_async16(uint32_t dst, const void* src) {
    asm volatile("cp.async.cg.shared.global [%0], [%1], 16;"
                 :: "r"(dst), "l"(src) : "memory");
}
__device__ __forceinline__ void cp_commit() {
    asm volatile("cp.async.commit_group;" ::: "memory");
}
template <int N>
__device__ __forceinline__ void cp_wait() {
    asm volatile("cp.async.wait_group %0;" :: "n"(N) : "memory");
}

__device__ __forceinline__ void ldmatrix4(uint32_t& r0, uint32_t& r1,
                                          uint32_t& r2, uint32_t& r3,
                                          uint32_t addr) {
    asm volatile("ldmatrix.sync.aligned.m8n8.x4.shared.b16 {%0,%1,%2,%3}, [%4];"
                 : "=r"(r0), "=r"(r1), "=r"(r2), "=r"(r3) : "r"(addr));
}

__device__ __forceinline__ void hmma(float* d,
                                     uint32_t a0, uint32_t a1, uint32_t a2, uint32_t a3,
                                     uint32_t b0, uint32_t b1) {
    asm volatile(
        "mma.sync.aligned.m16n8k16.row.col.f32.f16.f16.f32 "
        "{%0,%1,%2,%3}, {%4,%5,%6,%7}, {%8,%9}, {%0,%1,%2,%3};"
        : "+f"(d[0]), "+f"(d[1]), "+f"(d[2]), "+f"(d[3])
        : "r"(a0), "r"(a1), "r"(a2), "r"(a3), "r"(b0), "r"(b1));
}

// ---------------- fused prepass ----------------
// blocks [0, XCONV): x f32 -> fp16
// blocks [XCONV, ..): W packed-byte-in-int32 -> fp16 (q-8), 4 words -> 8 halves/thread
__global__ void prep_kernel(const float* __restrict__ x,
                            const int*   __restrict__ packed) {
    if (blockIdx.x < XCONV_BLOCKS) {
        int i = blockIdx.x * blockDim.x + threadIdx.x;         // float4 index
        float4 v = reinterpret_cast<const float4*>(x)[i];
        reinterpret_cast<__half2*>(g_xh)[2 * i + 0] = __floats2half2_rn(v.x, v.y);
        reinterpret_cast<__half2*>(g_xh)[2 * i + 1] = __floats2half2_rn(v.z, v.w);
    } else {
        int j = (blockIdx.x - XCONV_BLOCKS) * blockDim.x + threadIdx.x;  // uint4 idx
        uint4 p = reinterpret_cast<const uint4*>(packed)[j];   // words 4j..4j+3
        // word w (1 useful byte): halves (k even = hi nibble, k odd = lo nibble)
        // h2 = ((w>>4)&0xF | ((w&0xF)<<16) | 0x64006400) - 1032 (exact)
        uint4 o;
        uint32_t t;
        t = ((p.x >> 4) & 0xFu) | ((p.x & 0xFu) << 16) | 0x64006400u;
        o.x = dq_sub(t);
        t = ((p.y >> 4) & 0xFu) | ((p.y & 0xFu) << 16) | 0x64006400u;
        o.y = dq_sub(t);
        t = ((p.z >> 4) & 0xFu) | ((p.z & 0xFu) << 16) | 0x64006400u;
        o.z = dq_sub(t);
        t = ((p.w >> 4) & 0xFu) | ((p.w & 0xFu) << 16) | 0x64006400u;
        o.w = dq_sub(t);
        reinterpret_cast<uint4*>(g_wh)[j] = o;                 // halves 8j..8j+7
    }
}

// ---------------- HMMA GEMM ----------------
__global__ __launch_bounds__(256, 1)
void qgemm_kernel(const float* __restrict__ scale, float* __restrict__ y) {
    extern __shared__ __align__(1024) char sb[];
    const uint32_t sb32 = smem_u32(sb);

    const int tid = threadIdx.x;
    const int wid = tid >> 5;
    const int lid = tid & 31;
    const int N0 = blockIdx.x * BN;
    const int M0 = blockIdx.y * BM;

    const int wm = wid >> 2;            // 0..1 : m offset wm*64
    const int wn = wid & 3;             // 0..3 : n offset wn*64

    const __half* xb = g_xh + (size_t)M0 * K_DIM;
    const __half* wb = g_wh + (size_t)N0 * K_DIM;

    float acc[4][8][4];
    #pragma unroll
    for (int i = 0; i < 4; i++)
        #pragma unroll
        for (int j = 0; j < 8; j++)
            #pragma unroll
            for (int v = 0; v < 4; v++)
                acc[i][j][v] = 0.0f;

    // ---- prologue ----
    #pragma unroll
    for (int s = 0; s < STAGES - 1; s++) {
        const int k0 = s * KC;
        const uint32_t As = sb32 + s * STAGE_BYTES;
        const uint32_t Bs = As + A_BYTES;
        #pragma unroll
        for (int i = 0; i < 4; i++) {                   // A: 1024 segs
            int seg = tid + i * 256;
            int m = seg >> 3, j = seg & 7;
            cp_async16(As + sw128((uint32_t)(m * 128 + j * 16)),
                       xb + (size_t)m * K_DIM + k0 + j * 8);
        }
        #pragma unroll
        for (int i = 0; i < 8; i++) {                   // B: 2048 segs
            int seg = tid + i * 256;
            int n = seg >> 3, j = seg & 7;
            cp_async16(Bs + sw128((uint32_t)(n * 128 + j * 16)),
                       wb + (size_t)n * K_DIM + k0 + j * 8);
        }
        cp_commit();
    }

    const uint32_t a_warp = (uint32_t)(wm * 64 * 128);
    const uint32_t b_warp = (uint32_t)(wn * 64 * 128);
    const int ql  = lid >> 3;           // 0..3
    const int qr  = lid & 7;

    for (int c = 0; c < NCHUNK; c++) {
        const int fc = c + STAGES - 1;
        if (fc < NCHUNK) {
            const int fst = fc % STAGES;
            const int k0 = fc * KC;
            const uint32_t As = sb32 + fst * STAGE_BYTES;
            const uint32_t Bs = As + A_BYTES;
            #pragma unroll
            for (int i = 0; i < 4; i++) {
                int seg = tid + i * 256;
                int m = seg >> 3, j = seg & 7;
                cp_async16(As + sw128((uint32_t)(m * 128 + j * 16)),
                           xb + (size_t)m * K_DIM + k0 + j * 8);
            }
            #pragma unroll
            for (int i = 0; i < 8; i++) {
                int seg = tid + i * 256;
                int n = seg >> 3, j = seg & 7;
                cp_async16(Bs + sw128((uint32_t)(n * 128 + j * 16)),
                           wb + (size_t)n * K_DIM + k0 + j * 8);
            }
        }
        cp_commit();
        cp_wait<STAGES - 1>();
        __syncthreads();

        // ---- compute chunk c ----
        {
            const int st = c % STAGES;
            const uint32_t As = sb32 + st * STAGE_BYTES + a_warp;
            const uint32_t Bs = sb32 + st * STAGE_BYTES + A_BYTES + b_warp;

            #pragma unroll
            for (int kk = 0; kk < 4; kk++) {
                uint32_t a[4][4];
                #pragma unroll
                for (int i = 0; i < 4; i++) {
                    uint32_t addr = As + sw128((uint32_t)(
                        (i * 16 + (lid & 15)) * 128 + kk * 32 + (lid >> 4) * 16));
                    ldmatrix4(a[i][0], a[i][1], a[i][2], a[i][3], addr);
                }
                uint32_t b[8][2];
                #pragma unroll
                for (int g = 0; g < 4; g++) {
                    int row = g * 16 + (ql >> 1) * 8 + qr;
                    int kh  = ql & 1;
                    uint32_t addr = Bs + sw128((uint32_t)(
                        row * 128 + kk * 32 + kh * 16));
                    ldmatrix4(b[2*g][0], b[2*g][1], b[2*g+1][0], b[2*g+1][1], addr);
                }
                #pragma unroll
                for (int i = 0; i < 4; i++)
                    #pragma unroll
                    for (int jn = 0; jn < 8; jn++)
                        hmma(acc[i][jn], a[i][0], a[i][1], a[i][2], a[i][3],
                             b[jn][0], b[jn][1]);
            }
        }
        __syncthreads();
    }

    // ---- epilogue: scale + store fp32 ----
    #pragma unroll
    for (int i = 0; i < 4; i++) {
        int m0 = M0 + wm * 64 + i * 16 + (lid >> 2);
        #pragma unroll
        for (int j = 0; j < 8; j++) {
            int n = N0 + wn * 64 + j * 8 + 2 * (lid & 3);
            float2 s = *reinterpret_cast<const float2*>(scale + n);
            float2 o0, o1;
            o0.x = acc[i][j][0] * s.x;
            o0.y = acc[i][j][1] * s.y;
            o1.x = acc[i][j][2] * s.x;
            o1.y = acc[i][j][3] * s.y;
            *reinterpret_cast<float2*>(y + (size_t)m0 * N_DIM + n) = o0;
            *reinterpret_cast<float2*>(y + (size_t)(m0 + 8) * N_DIM + n) = o1;
        }
    }
}

// ---------------- launch ----------------
extern "C" void kernel_launch(void* const* d_in, const int* in_sizes, int n_in,
                              void* d_out, int out_size) {
    const float* x      = (const float*)d_in[0];
    const int*   packed = (const int*)  d_in[1];
    const float* scale  = (const float*)d_in[2];
    float*       y      = (float*)d_out;

    prep_kernel<<<PREP_BLOCKS, 256>>>(x, packed);

    static bool attr_set = false;
    if (!attr_set) {
        cudaFuncSetAttribute(qgemm_kernel,
                             cudaFuncAttributeMaxDynamicSharedMemorySize, SMEM_BYTES);
        attr_set = true;
    }
    dim3 grid(N_DIM / BN, M_DIM / BM);   // (32, 4) = 128 CTAs
    qgemm_kernel<<<grid, 256, SMEM_BYTES>>>(scale, y);
}

// round 7
// speedup vs baseline: 7.3592x; 1.0004x over previous
#include <cuda_runtime.h>
#include <cuda_fp16.h>
#include <cstdint>

// QuantizedLinear on GB300 (sm_103a harness, compute_103 virtual arch -> legacy
// mma.sync.m16n8k16 path; tcgen05 PTX rejected by ptxas at this target).
//   y[b,o] = scale[o] * sum_k x[b,k] * (q[o,k] - 8)
//
// Round 7: occupancy + barrier attack.
//  - prep: fused x->fp16 (8 MB) and W->fp16 dequant (134 MB), exact q-8.
//  - GEMM: BM=128, BN=128, KC=64, 3-stage cp.async pipeline, ONE barrier per
//    chunk (loads for chunk c+2 go into the stage consumed at chunk c-1).
//    8 warps @ 64x32, <=128 regs, 96 KB smem -> 2 CTAs/SM, grid 256 = 1 wave.

static constexpr int M_DIM = 512;
static constexpr int N_DIM = 8192;
static constexpr int K_DIM = 8192;

static constexpr int BM = 128;
static constexpr int BN = 128;
static constexpr int KC = 64;
static constexpr int STAGES = 3;
static constexpr int NCHUNK = K_DIM / KC;          // 128

static constexpr int A_BYTES = BM * 128;           // 16 KB (fp16 SW128)
static constexpr int B_BYTES = BN * 128;           // 16 KB (fp16 SW128)
static constexpr int STAGE_BYTES = A_BYTES + B_BYTES;      // 32 KB
static constexpr int SMEM_BYTES  = STAGES * STAGE_BYTES;   // 96 KB

// prep kernel partition
static constexpr int XCONV_BLOCKS = (M_DIM * K_DIM / 4) / 256;          // 4096
static constexpr int WDEQ_BLOCKS  = (N_DIM * (K_DIM / 2) / 4) / 256;    // 4M words /4/256
static constexpr int PREP_BLOCKS  = XCONV_BLOCKS + WDEQ_BLOCKS;

// -------- scratch (device globals; no runtime allocation) --------
__device__ __align__(16) __half g_xh[(size_t)M_DIM * K_DIM];    // 8 MB
__device__ __align__(16) __half g_wh[(size_t)N_DIM * K_DIM];    // 134 MB

// ---------------- helpers ----------------
__device__ __forceinline__ uint32_t smem_u32(const void* p) {
    uint32_t a;
    asm("{ .reg .u64 t; cvta.to.shared.u64 t, %1; cvt.u32.u64 %0, t; }"
        : "=r"(a) : "l"(p));
    return a;
}

__device__ __forceinline__ uint32_t sw128(uint32_t off) {
    return off ^ ((off >> 3) & 0x70u);
}

// (1024+q) - 1032 = q - 8, exact in fp16, both lanes
__device__ __forceinline__ uint32_t dq_sub(uint32_t v) {
    uint32_t r;
    asm("sub.rn.f16x2 %0, %1, %2;" : "=r"(r) : "r"(v), "r"(0x64086408u));
    return r;
}

__device__ __forceinline__ void cp_async16(uint32_t dst, const void* src) {
    asm volatile("cp.async.cg.shared.global [%0], [%1], 16;"
                 :: "r"(dst), "l"(src) : "memory");
}
__device__ __forceinline__ void cp_commit() {
    asm volatile("cp.async.commit_group;" ::: "memory");
}
template <int N>
__device__ __forceinline__ void cp_wait() {
    asm volatile("cp.async.wait_group %0;" :: "n"(N) : "memory");
}

__device__ __forceinline__ void ldmatrix4(uint32_t& r0, uint32_t& r1,
                                          uint32_t& r2, uint32_t& r3,
                                          uint32_t addr) {
    asm volatile("ldmatrix.sync.aligned.m8n8.x4.shared.b16 {%0,%1,%2,%3}, [%4];"
                 : "=r"(r0), "=r"(r1), "=r"(r2), "=r"(r3) : "r"(addr));
}

__device__ __forceinline__ void hmma(float* d,
                                     uint32_t a0, uint32_t a1, uint32_t a2, uint32_t a3,
                                     uint32_t b0, uint32_t b1) {
    asm volatile(
        "mma.sync.aligned.m16n8k16.row.col.f32.f16.f16.f32 "
        "{%0,%1,%2,%3}, {%4,%5,%6,%7}, {%8,%9}, {%0,%1,%2,%3};"
        : "+f"(d[0]), "+f"(d[1]), "+f"(d[2]), "+f"(d[3])
        : "r"(a0), "r"(a1), "r"(a2), "r"(a3), "r"(b0), "r"(b1));
}

// ---------------- fused prepass ----------------
__global__ void prep_kernel(const float* __restrict__ x,
                            const int*   __restrict__ packed) {
    if (blockIdx.x < XCONV_BLOCKS) {
        int i = blockIdx.x * blockDim.x + threadIdx.x;         // float4 index
        float4 v = reinterpret_cast<const float4*>(x)[i];
        reinterpret_cast<__half2*>(g_xh)[2 * i + 0] = __floats2half2_rn(v.x, v.y);
        reinterpret_cast<__half2*>(g_xh)[2 * i + 1] = __floats2half2_rn(v.z, v.w);
    } else {
        int j = (blockIdx.x - XCONV_BLOCKS) * blockDim.x + threadIdx.x;  // uint4 idx
        uint4 p = reinterpret_cast<const uint4*>(packed)[j];   // words 4j..4j+3
        uint4 o;
        uint32_t t;
        t = ((p.x >> 4) & 0xFu) | ((p.x & 0xFu) << 16) | 0x64006400u;
        o.x = dq_sub(t);
        t = ((p.y >> 4) & 0xFu) | ((p.y & 0xFu) << 16) | 0x64006400u;
        o.y = dq_sub(t);
        t = ((p.z >> 4) & 0xFu) | ((p.z & 0xFu) << 16) | 0x64006400u;
        o.z = dq_sub(t);
        t = ((p.w >> 4) & 0xFu) | ((p.w & 0xFu) << 16) | 0x64006400u;
        o.w = dq_sub(t);
        reinterpret_cast<uint4*>(g_wh)[j] = o;                 // halves 8j..8j+7
    }
}

// ---------------- HMMA GEMM ----------------
__global__ __launch_bounds__(256, 2)
void qgemm_kernel(const float* __restrict__ scale, float* __restrict__ y) {
    extern __shared__ __align__(1024) char sb[];
    const uint32_t sb32 = smem_u32(sb);

    const int tid = threadIdx.x;
    const int wid = tid >> 5;
    const int lid = tid & 31;
    const int N0 = blockIdx.x * BN;
    const int M0 = blockIdx.y * BM;

    const int wm = wid >> 2;            // 0..1 : m offset wm*64
    const int wn = wid & 3;             // 0..3 : n offset wn*32

    const __half* xb = g_xh + (size_t)M0 * K_DIM;
    const __half* wb = g_wh + (size_t)N0 * K_DIM;

    float acc[4][4][4];
    #pragma unroll
    for (int i = 0; i < 4; i++)
        #pragma unroll
        for (int j = 0; j < 4; j++)
            #pragma unroll
            for (int v = 0; v < 4; v++)
                acc[i][j][v] = 0.0f;

    // ---- prologue: stages 0..S-2 <- chunks 0..S-2 ----
    #pragma unroll
    for (int s = 0; s < STAGES - 1; s++) {
        const int k0 = s * KC;
        const uint32_t As = sb32 + s * STAGE_BYTES;
        const uint32_t Bs = As + A_BYTES;
        #pragma unroll
        for (int i = 0; i < 4; i++) {                   // A: 1024 segs
            int seg = tid + i * 256;
            int m = seg >> 3, j = seg & 7;
            cp_async16(As + sw128((uint32_t)(m * 128 + j * 16)),
                       xb + (size_t)m * K_DIM + k0 + j * 8);
        }
        #pragma unroll
        for (int i = 0; i < 4; i++) {                   // B: 1024 segs
            int seg = tid + i * 256;
            int n = seg >> 3, j = seg & 7;
            cp_async16(Bs + sw128((uint32_t)(n * 128 + j * 16)),
                       wb + (size_t)n * K_DIM + k0 + j * 8);
        }
        cp_commit();
    }

    const uint32_t a_warp = (uint32_t)(wm * 64 * 128);
    const uint32_t b_warp = (uint32_t)(wn * 32 * 128);
    const int ql = lid >> 3;            // 0..3
    const int qr = lid & 7;

    for (int c = 0; c < NCHUNK; c++) {
        // chunk c's cp.async group is the oldest of STAGES-1 in flight
        cp_wait<STAGES - 2>();
        __syncthreads();

        // ---- issue loads for chunk c+S-1 into stage (c-1)%S (consumed at c-1) ----
        const int fc = c + STAGES - 1;
        if (fc < NCHUNK) {
            const int fst = fc % STAGES;
            const int k0 = fc * KC;
            const uint32_t As = sb32 + fst * STAGE_BYTES;
            const uint32_t Bs = As + A_BYTES;
            #pragma unroll
            for (int i = 0; i < 4; i++) {
                int seg = tid + i * 256;
                int m = seg >> 3, j = seg & 7;
                cp_async16(As + sw128((uint32_t)(m * 128 + j * 16)),
                           xb + (size_t)m * K_DIM + k0 + j * 8);
            }
            #pragma unroll
            for (int i = 0; i < 4; i++) {
                int seg = tid + i * 256;
                int n = seg >> 3, j = seg & 7;
                cp_async16(Bs + sw128((uint32_t)(n * 128 + j * 16)),
                           wb + (size_t)n * K_DIM + k0 + j * 8);
            }
        }
        cp_commit();

        // ---- compute chunk c ----
        {
            const int st = c % STAGES;
            const uint32_t As = sb32 + st * STAGE_BYTES + a_warp;
            const uint32_t Bs = sb32 + st * STAGE_BYTES + A_BYTES + b_warp;

            #pragma unroll
            for (int kk = 0; kk < 4; kk++) {
                uint32_t a[4][4];
                #pragma unroll
                for (int i = 0; i < 4; i++) {
                    uint32_t addr = As + sw128((uint32_t)(
                        (i * 16 + (lid & 15)) * 128 + kk * 32 + (lid >> 4) * 16));
                    ldmatrix4(a[i][0], a[i][1], a[i][2], a[i][3], addr);
                }
                uint32_t b[4][2];
                #pragma unroll
                for (int g = 0; g < 2; g++) {
                    int row = g * 16 + (ql >> 1) * 8 + qr;
                    int kh  = ql & 1;
                    uint32_t addr = Bs + sw128((uint32_t)(
                        row * 128 + kk * 32 + kh * 16));
                    ldmatrix4(b[2*g][0], b[2*g][1], b[2*g+1][0], b[2*g+1][1], addr);
                }
                #pragma unroll
                for (int i = 0; i < 4; i++)
                    #pragma unroll
                    for (int jn = 0; jn < 4; jn++)
                        hmma(acc[i][jn], a[i][0], a[i][1], a[i][2], a[i][3],
                             b[jn][0], b[jn][1]);
            }
        }
    }

    // ---- epilogue: scale + store fp32 ----
    #pragma unroll
    for (int i = 0; i < 4; i++) {
        int m0 = M0 + wm * 64 + i * 16 + (lid >> 2);
        #pragma unroll
        for (int j = 0; j < 4; j++) {
            int n = N0 + wn * 32 + j * 8 + 2 * (lid & 3);
            float2 s = *reinterpret_cast<const float2*>(scale + n);
            float2 o0, o1;
            o0.x = acc[i][j][0] * s.x;
            o0.y = acc[i][j][1] * s.y;
            o1.x = acc[i][j][2] * s.x;
            o1.y = acc[i][j][3] * s.y;
            *reinterpret_cast<float2*>(y + (size_t)m0 * N_DIM + n) = o0;
            *reinterpret_cast<float2*>(y + (size_t)(m0 + 8) * N_DIM + n) = o1;
        }
    }
}

// ---------------- launch ----------------
extern "C" void kernel_launch(void* const* d_in, const int* in_sizes, int n_in,
                              void* d_out, int out_size) {
    const float* x      = (const float*)d_in[0];
    const int*   packed = (const int*)  d_in[1];
    const float* scale  = (const float*)d_in[2];
    float*       y      = (float*)d_out;

    prep_kernel<<<PREP_BLOCKS, 256>>>(x, packed);

    static bool attr_set = false;
    if (!attr_set) {
        cudaFuncSetAttribute(qgemm_kernel,
                             cudaFuncAttributeMaxDynamicSharedMemorySize, SMEM_BYTES);
        attr_set = true;
    }
    dim3 grid(N_DIM / BN, M_DIM / BM);   // (64, 4) = 256 CTAs, 2/SM, 1 wave
    qgemm_kernel<<<grid, 256, SMEM_BYTES>>>(scale, y);
}

// round 8
// speedup vs baseline: 7.7013x; 1.0465x over previous
#include <cuda_runtime.h>
#include <cuda_fp16.h>
#include <cstdint>

// QuantizedLinear on GB300 (sm_103a harness, compute_103 virtual arch -> legacy
// mma.sync.m16n8k16 path; tcgen05 PTX rejected by ptxas at this target).
//   y[b,o] = scale[o] * sum_k x[b,k] * (q[o,k] - 8)
//
// Round 8: 64x64 warp tiles (best smem-per-MAC) at 2 CTAs/SM with full-chip
// coverage: CTA = 128 threads (4 warps, 2x2), tile 128x128, KC=64, 3-stage
// cp.async pipeline, one barrier per chunk. Grid 256 -> 2 CTAs/SM on 148 SMs.
// Prep unchanged: fused x->fp16 (8 MB) + W->fp16 dequant (134 MB), exact q-8.

static constexpr int M_DIM = 512;
static constexpr int N_DIM = 8192;
static constexpr int K_DIM = 8192;

static constexpr int BM = 128;
static constexpr int BN = 128;
static constexpr int KC = 64;
static constexpr int STAGES = 3;
static constexpr int NCHUNK = K_DIM / KC;          // 128
static constexpr int NTHREADS = 128;               // 4 warps, 2x2

static constexpr int A_BYTES = BM * 128;           // 16 KB (fp16 SW128)
static constexpr int B_BYTES = BN * 128;           // 16 KB (fp16 SW128)
static constexpr int STAGE_BYTES = A_BYTES + B_BYTES;      // 32 KB
static constexpr int SMEM_BYTES  = STAGES * STAGE_BYTES;   // 96 KB

// prep kernel partition
static constexpr int XCONV_BLOCKS = (M_DIM * K_DIM / 4) / 256;          // 4096
static constexpr int WDEQ_BLOCKS  = (N_DIM * (K_DIM / 2) / 4) / 256;
static constexpr int PREP_BLOCKS  = XCONV_BLOCKS + WDEQ_BLOCKS;

// -------- scratch (device globals; no runtime allocation) --------
__device__ __align__(16) __half g_xh[(size_t)M_DIM * K_DIM];    // 8 MB
__device__ __align__(16) __half g_wh[(size_t)N_DIM * K_DIM];    // 134 MB

// ---------------- helpers ----------------
__device__ __forceinline__ uint32_t smem_u32(const void* p) {
    uint32_t a;
    asm("{ .reg .u64 t; cvta.to.shared.u64 t, %1; cvt.u32.u64 %0, t; }"
        : "=r"(a) : "l"(p));
    return a;
}

__device__ __forceinline__ uint32_t sw128(uint32_t off) {
    return off ^ ((off >> 3) & 0x70u);
}

// (1024+q) - 1032 = q - 8, exact in fp16, both lanes
__device__ __forceinline__ uint32_t dq_sub(uint32_t v) {
    uint32_t r;
    asm("sub.rn.f16x2 %0, %1, %2;" : "=r"(r) : "r"(v), "r"(0x64086408u));
    return r;
}

__device__ __forceinline__ void cp_async16(uint32_t dst, const void* src) {
    asm volatile("cp.async.cg.shared.global [%0], [%1], 16;"
                 :: "r"(dst), "l"(src) : "memory");
}
__device__ __forceinline__ void cp_commit() {
    asm volatile("cp.async.commit_group;" ::: "memory");
}
template <int N>
__device__ __forceinline__ void cp_wait() {
    asm volatile("cp.async.wait_group %0;" :: "n"(N) : "memory");
}

__device__ __forceinline__ void ldmatrix4(uint32_t& r0, uint32_t& r1,
                                          uint32_t& r2, uint32_t& r3,
                                          uint32_t addr) {
    asm volatile("ldmatrix.sync.aligned.m8n8.x4.shared.b16 {%0,%1,%2,%3}, [%4];"
                 : "=r"(r0), "=r"(r1), "=r"(r2), "=r"(r3) : "r"(addr));
}

__device__ __forceinline__ void hmma(float* d,
                                     uint32_t a0, uint32_t a1, uint32_t a2, uint32_t a3,
                                     uint32_t b0, uint32_t b1) {
    asm volatile(
        "mma.sync.aligned.m16n8k16.row.col.f32.f16.f16.f32 "
        "{%0,%1,%2,%3}, {%4,%5,%6,%7}, {%8,%9}, {%0,%1,%2,%3};"
        : "+f"(d[0]), "+f"(d[1]), "+f"(d[2]), "+f"(d[3])
        : "r"(a0), "r"(a1), "r"(a2), "r"(a3), "r"(b0), "r"(b1));
}

// ---------------- fused prepass ----------------
__global__ void prep_kernel(const float* __restrict__ x,
                            const int*   __restrict__ packed) {
    if (blockIdx.x < XCONV_BLOCKS) {
        int i = blockIdx.x * blockDim.x + threadIdx.x;         // float4 index
        float4 v = reinterpret_cast<const float4*>(x)[i];
        reinterpret_cast<__half2*>(g_xh)[2 * i + 0] = __floats2half2_rn(v.x, v.y);
        reinterpret_cast<__half2*>(g_xh)[2 * i + 1] = __floats2half2_rn(v.z, v.w);
    } else {
        int j = (blockIdx.x - XCONV_BLOCKS) * blockDim.x + threadIdx.x;  // uint4 idx
        uint4 p = reinterpret_cast<const uint4*>(packed)[j];   // words 4j..4j+3
        uint4 o;
        uint32_t t;
        t = ((p.x >> 4) & 0xFu) | ((p.x & 0xFu) << 16) | 0x64006400u;
        o.x = dq_sub(t);
        t = ((p.y >> 4) & 0xFu) | ((p.y & 0xFu) << 16) | 0x64006400u;
        o.y = dq_sub(t);
        t = ((p.z >> 4) & 0xFu) | ((p.z & 0xFu) << 16) | 0x64006400u;
        o.z = dq_sub(t);
        t = ((p.w >> 4) & 0xFu) | ((p.w & 0xFu) << 16) | 0x64006400u;
        o.w = dq_sub(t);
        reinterpret_cast<uint4*>(g_wh)[j] = o;                 // halves 8j..8j+7
    }
}

// ---------------- HMMA GEMM ----------------
__global__ __launch_bounds__(NTHREADS, 2)
void qgemm_kernel(const float* __restrict__ scale, float* __restrict__ y) {
    extern __shared__ __align__(1024) char sb[];
    const uint32_t sb32 = smem_u32(sb);

    const int tid = threadIdx.x;
    const int wid = tid >> 5;
    const int lid = tid & 31;
    const int N0 = blockIdx.x * BN;
    const int M0 = blockIdx.y * BM;

    const int wm = wid >> 1;            // 0..1 : m offset wm*64
    const int wn = wid & 1;             // 0..1 : n offset wn*64

    const __half* xb = g_xh + (size_t)M0 * K_DIM;
    const __half* wb = g_wh + (size_t)N0 * K_DIM;

    float acc[4][8][4];
    #pragma unroll
    for (int i = 0; i < 4; i++)
        #pragma unroll
        for (int j = 0; j < 8; j++)
            #pragma unroll
            for (int v = 0; v < 4; v++)
                acc[i][j][v] = 0.0f;

    // ---- prologue: stages 0..S-2 <- chunks 0..S-2 ----
    #pragma unroll
    for (int s = 0; s < STAGES - 1; s++) {
        const int k0 = s * KC;
        const uint32_t As = sb32 + s * STAGE_BYTES;
        const uint32_t Bs = As + A_BYTES;
        #pragma unroll
        for (int i = 0; i < 8; i++) {                   // A: 1024 segs
            int seg = tid + i * NTHREADS;
            int m = seg >> 3, j = seg & 7;
            cp_async16(As + sw128((uint32_t)(m * 128 + j * 16)),
                       xb + (size_t)m * K_DIM + k0 + j * 8);
        }
        #pragma unroll
        for (int i = 0; i < 8; i++) {                   // B: 1024 segs
            int seg = tid + i * NTHREADS;
            int n = seg >> 3, j = seg & 7;
            cp_async16(Bs + sw128((uint32_t)(n * 128 + j * 16)),
                       wb + (size_t)n * K_DIM + k0 + j * 8);
        }
        cp_commit();
    }

    const uint32_t a_warp = (uint32_t)(wm * 64 * 128);
    const uint32_t b_warp = (uint32_t)(wn * 64 * 128);
    const int ql = lid >> 3;            // 0..3
    const int qr = lid & 7;

    for (int c = 0; c < NCHUNK; c++) {
        cp_wait<STAGES - 2>();
        __syncthreads();

        // ---- issue loads for chunk c+S-1 into stage (c-1)%S (freed at c-1) ----
        const int fc = c + STAGES - 1;
        if (fc < NCHUNK) {
            const int fst = fc % STAGES;
            const int k0 = fc * KC;
            const uint32_t As = sb32 + fst * STAGE_BYTES;
            const uint32_t Bs = As + A_BYTES;
            #pragma unroll
            for (int i = 0; i < 8; i++) {
                int seg = tid + i * NTHREADS;
                int m = seg >> 3, j = seg & 7;
                cp_async16(As + sw128((uint32_t)(m * 128 + j * 16)),
                           xb + (size_t)m * K_DIM + k0 + j * 8);
            }
            #pragma unroll
            for (int i = 0; i < 8; i++) {
                int seg = tid + i * NTHREADS;
                int n = seg >> 3, j = seg & 7;
                cp_async16(Bs + sw128((uint32_t)(n * 128 + j * 16)),
                           wb + (size_t)n * K_DIM + k0 + j * 8);
            }
        }
        cp_commit();

        // ---- compute chunk c ----
        {
            const int st = c % STAGES;
            const uint32_t As = sb32 + st * STAGE_BYTES + a_warp;
            const uint32_t Bs = sb32 + st * STAGE_BYTES + A_BYTES + b_warp;

            #pragma unroll
            for (int kk = 0; kk < 4; kk++) {
                uint32_t a[4][4];
                #pragma unroll
                for (int i = 0; i < 4; i++) {
                    uint32_t addr = As + sw128((uint32_t)(
                        (i * 16 + (lid & 15)) * 128 + kk * 32 + (lid >> 4) * 16));
                    ldmatrix4(a[i][0], a[i][1], a[i][2], a[i][3], addr);
                }
                uint32_t b[8][2];
                #pragma unroll
                for (int g = 0; g < 4; g++) {
                    int row = g * 16 + (ql >> 1) * 8 + qr;
                    int kh  = ql & 1;
                    uint32_t addr = Bs + sw128((uint32_t)(
                        row * 128 + kk * 32 + kh * 16));
                    ldmatrix4(b[2*g][0], b[2*g][1], b[2*g+1][0], b[2*g+1][1], addr);
                }
                #pragma unroll
                for (int i = 0; i < 4; i++)
                    #pragma unroll
                    for (int jn = 0; jn < 8; jn++)
                        hmma(acc[i][jn], a[i][0], a[i][1], a[i][2], a[i][3],
                             b[jn][0], b[jn][1]);
            }
        }
    }

    // ---- epilogue: scale + store fp32 ----
    #pragma unroll
    for (int i = 0; i < 4; i++) {
        int m0 = M0 + wm * 64 + i * 16 + (lid >> 2);
        #pragma unroll
        for (int j = 0; j < 8; j++) {
            int n = N0 + wn * 64 + j * 8 + 2 * (lid & 3);
            float2 s = *reinterpret_cast<const float2*>(scale + n);
            float2 o0, o1;
            o0.x = acc[i][j][0] * s.x;
            o0.y = acc[i][j][1] * s.y;
            o1.x = acc[i][j][2] * s.x;
            o1.y = acc[i][j][3] * s.y;
            *reinterpret_cast<float2*>(y + (size_t)m0 * N_DIM + n) = o0;
            *reinterpret_cast<float2*>(y + (size_t)(m0 + 8) * N_DIM + n) = o1;
        }
    }
}

// ---------------- launch ----------------
extern "C" void kernel_launch(void* const* d_in, const int* in_sizes, int n_in,
                              void* d_out, int out_size) {
    const float* x      = (const float*)d_in[0];
    const int*   packed = (const int*)  d_in[1];
    const float* scale  = (const float*)d_in[2];
    float*       y      = (float*)d_out;

    prep_kernel<<<PREP_BLOCKS, 256>>>(x, packed);

    static bool attr_set = false;
    if (!attr_set) {
        cudaFuncSetAttribute(qgemm_kernel,
                             cudaFuncAttributeMaxDynamicSharedMemorySize, SMEM_BYTES);
        attr_set = true;
    }
    dim3 grid(N_DIM / BN, M_DIM / BM);   // (64, 4) = 256 CTAs, 2/SM, full chip
    qgemm_kernel<<<grid, NTHREADS, SMEM_BYTES>>>(scale, y);
}